// round 6
// baseline (speedup 1.0000x reference)
#include <cuda_runtime.h>
#include <cuda_bf16.h>
#include <cstdint>

#define BB 32
#define TT 4096
#define PP 512
#define WW 128
#define NMEL 80
#define FILT 256
#define PDIM 64
#define KK 9
#define PAD 4

#define STR 40                        // smem row stride (bf16), conflict-free
#define A_ROWS 136                    // 128 + 2*PAD halo
#define A_CP 5440                     // A_ROWS*STR elems per copy
#define B_CP 5120                     // 128*STR elems per copy
// elem offsets: A chunkbuf k at k*(2*A_CP) (hi, then mid); B ring r at OFF_B + r*(2*B_CP)
#define OFF_B 21760
#define CONV_SMEM ((OFF_B + 3 * 2 * B_CP) * 2)    // 104960 bytes -> 2 CTAs/SM

// ---------------- device scratch ----------------------------------------------------
__device__ __nv_bfloat16 g_melhi[(size_t)BB * TT * 96];
__device__ __nv_bfloat16 g_melmid[(size_t)BB * TT * 96];
__device__ __nv_bfloat16 g_x1hi[(size_t)BB * TT * FILT];
__device__ __nv_bfloat16 g_x1mid[(size_t)BB * TT * FILT];
__device__ float g_craw[(size_t)BB * TT * FILT];
__device__ float g_x2[(size_t)BB * TT * FILT];
__device__ __nv_bfloat16 g_w1h[KK * FILT * 96];
__device__ __nv_bfloat16 g_w1m[KK * FILT * 96];
__device__ __nv_bfloat16 g_w2h[KK * FILT * FILT];
__device__ __nv_bfloat16 g_w2m[KK * FILT * FILT];
__device__ float g_ph[(size_t)BB * PP * FILT];
__device__ float g_wd[(size_t)BB * WW * FILT];
__device__ float g_z [(size_t)BB * WW * PDIM];
__device__ int   g_pcum[BB * PP];
__device__ int   g_wcum[BB * WW];

// ---------------- helpers ------------------------------------------------------------
__device__ __forceinline__ uint32_t smem_u32(const void* p) {
    return (uint32_t)__cvta_generic_to_shared(p);
}
#define CP16(dst_u32, src_ptr) \
    asm volatile("cp.async.cg.shared.global [%0], [%1], 16;" :: "r"(dst_u32), "l"(src_ptr) : "memory")
#define CP_COMMIT() asm volatile("cp.async.commit_group;" ::: "memory")
#define CP_WAIT0()  asm volatile("cp.async.wait_group 0;" ::: "memory")
#define CP_WAIT1()  asm volatile("cp.async.wait_group 1;" ::: "memory")

#define MMA_BF16(d, a, b) \
    asm volatile("mma.sync.aligned.m16n8k16.row.col.f32.bf16.bf16.f32 " \
        "{%0,%1,%2,%3},{%4,%5,%6,%7},{%8,%9},{%0,%1,%2,%3};" \
        : "+f"((d)[0]), "+f"((d)[1]), "+f"((d)[2]), "+f"((d)[3]) \
        : "r"((a)[0]), "r"((a)[1]), "r"((a)[2]), "r"((a)[3]), "r"((b)[0]), "r"((b)[1]))

#define LDM4(r0, r1, r2, r3, addr) \
    asm volatile("ldmatrix.sync.aligned.m8n8.x4.shared.b16 {%0,%1,%2,%3}, [%4];" \
        : "=r"(r0), "=r"(r1), "=r"(r2), "=r"(r3) : "r"(addr))

__device__ __forceinline__ uint32_t pack_hi2(float x0, float x1) {
    __nv_bfloat162 t(__float2bfloat16_rn(x0), __float2bfloat16_rn(x1));
    return *reinterpret_cast<uint32_t*>(&t);
}
__device__ __forceinline__ uint32_t pack_mid2(float x0, float x1) {
    float h0 = __bfloat162float(__float2bfloat16_rn(x0));
    float h1 = __bfloat162float(__float2bfloat16_rn(x1));
    __nv_bfloat162 t(__float2bfloat16_rn(x0 - h0), __float2bfloat16_rn(x1 - h1));
    return *reinterpret_cast<uint32_t*>(&t);
}

// ---------------- prep kernels -------------------------------------------------------
__global__ void mel_split_kernel(const float* __restrict__ mels) {
    size_t i = (size_t)blockIdx.x * blockDim.x + threadIdx.x;
    if (i < (size_t)BB * TT * 96) {
        size_t t = i / 96;
        int ci = (int)(i % 96);
        float x = (ci < NMEL) ? mels[t * NMEL + ci] : 0.f;
        __nv_bfloat16 h = __float2bfloat16_rn(x);
        g_melhi[i] = h;
        g_melmid[i] = __float2bfloat16_rn(x - __bfloat162float(h));
    }
}
template <int CIN, int CINP>
__global__ void wsplit_kernel(const float* __restrict__ w,
                              __nv_bfloat16* __restrict__ wh,
                              __nv_bfloat16* __restrict__ wm) {
    int i = blockIdx.x * blockDim.x + threadIdx.x;      // [tap][co][ci-padded]
    if (i < KK * FILT * CINP) {
        int ci = i % CINP;
        int co = (i / CINP) % FILT;
        int tap = i / (CINP * FILT);
        float x = (ci < CIN) ? w[(co * CIN + ci) * KK + tap] : 0.f;
        __nv_bfloat16 h = __float2bfloat16_rn(x);
        wh[i] = h;
        wm[i] = __float2bfloat16_rn(x - __bfloat162float(h));
    }
}
__global__ void scan_kernel(const int* __restrict__ dur, const int* __restrict__ wpl) {
    int b = blockIdx.x, lane = threadIdx.x;             // 32 threads/block
    int v[16], s = 0;
#pragma unroll
    for (int i = 0; i < 16; i++) { v[i] = dur[b * PP + lane * 16 + i]; s += v[i]; }
    int inc = s;
#pragma unroll
    for (int off = 1; off < 32; off <<= 1) {
        int t = __shfl_up_sync(0xffffffffu, inc, off);
        if (lane >= off) inc += t;
    }
    int base = inc - s, run = 0;
#pragma unroll
    for (int i = 0; i < 16; i++) { run += v[i]; g_pcum[b * PP + lane * 16 + i] = base + run; }
    int w[4]; s = 0;
#pragma unroll
    for (int i = 0; i < 4; i++) { w[i] = wpl[b * WW + lane * 4 + i]; s += w[i]; }
    inc = s;
#pragma unroll
    for (int off = 1; off < 32; off <<= 1) {
        int t = __shfl_up_sync(0xffffffffu, inc, off);
        if (lane >= off) inc += t;
    }
    base = inc - s; run = 0;
#pragma unroll
    for (int i = 0; i < 4; i++) { run += w[i]; g_wcum[b * WW + lane * 4 + i] = base + run; }
}

// ---------------- conv via bf16x3 mma.sync, 3-deep B ring, 2 CTAs/SM -----------------
template <int NCH>     // cin chunks of 32: conv1=3 (padded 96), conv2=8
__global__ void __launch_bounds__(256, 2) conv_mma(
    const __nv_bfloat16* __restrict__ Ahi, const __nv_bfloat16* __restrict__ Amid,
    const __nv_bfloat16* __restrict__ Bhi, const __nv_bfloat16* __restrict__ Bmid,
    float* __restrict__ outc)
{
    constexpr int CINP = NCH * 32;
    constexpr int NST = NCH * KK;
    extern __shared__ __nv_bfloat16 smbf[];

    const int tid = threadIdx.x;
    const int wid = tid >> 5, lane = tid & 31;
    const int wm = wid & 1, wn = wid >> 1;              // 2m x 4n warps
    const int t0 = blockIdx.x * 128;
    const int n0 = blockIdx.y * 128;
    const size_t bT = (size_t)blockIdx.z * TT;
    const uint32_t smb = smem_u32(smbf);

    float acc[4][4][4];
#pragma unroll
    for (int mt = 0; mt < 4; mt++)
#pragma unroll
        for (int nt = 0; nt < 4; nt++)
#pragma unroll
            for (int q = 0; q < 4; q++) acc[mt][nt][q] = 0.f;

    // ldmatrix lane offsets
    const int a_l = ((lane >> 3) & 1) * 8 + (lane & 7);
    const int a_k = (lane >> 4) * 8;
    const int b_l = (lane >> 4) * 8 + (lane & 7);
    const int b_k = ((lane >> 3) & 1) * 8;
    uint32_t aoff[4], boff[2];
#pragma unroll
    for (int mt = 0; mt < 4; mt++)
        aoff[mt] = ((wm * 64 + mt * 16 + a_l) * STR + a_k) * 2;
#pragma unroll
    for (int np = 0; np < 2; np++)
        boff[np] = ((wn * 32 + np * 16 + b_l) * STR + b_k) * 2;

    auto issue_loads = [&](int s) {
        int chunk = s / KK, tap = s - chunk * KK;
        __nv_bfloat16* sB = smbf + OFF_B + (s % 3) * (2 * B_CP);
#pragma unroll
        for (int j = 0; j < 4; j++) {
            int q = tid + j * 256;                      // 0..1023
            int copy = q >> 9, rc = q & 511;
            int row = rc >> 2, c16 = rc & 3;
            const __nv_bfloat16* src = (copy ? Bmid : Bhi)
                + ((size_t)tap * FILT + n0 + row) * CINP + chunk * 32 + c16 * 8;
            CP16(smem_u32(sB + copy * B_CP + row * STR + c16 * 8), src);
        }
        if (tap == 0) {
            __nv_bfloat16* sA = smbf + (chunk & 1) * (2 * A_CP);
#pragma unroll
            for (int j = 0; j < 5; j++) {
                int q = tid + j * 256;
                if (q < 1088) {
                    int copy = (q >= 544) ? 1 : 0;
                    int rem = q - copy * 544;
                    int row = rem >> 2, c16 = rem & 3;
                    int trow = t0 + row - PAD;
                    __nv_bfloat16* dst = sA + copy * A_CP + row * STR + c16 * 8;
                    if (trow >= 0 && trow < TT) {
                        const __nv_bfloat16* src = (copy ? Amid : Ahi)
                            + (bT + trow) * CINP + chunk * 32 + c16 * 8;
                        CP16(smem_u32(dst), src);
                    } else {
                        *(uint4*)dst = make_uint4(0, 0, 0, 0);
                    }
                }
            }
        }
    };

    issue_loads(0); CP_COMMIT();
    issue_loads(1); CP_COMMIT();

    for (int s = 0; s < NST; s++) {
        if (s + 1 < NST) CP_WAIT1(); else CP_WAIT0();
        __syncthreads();
        if (s + 2 < NST) { issue_loads(s + 2); CP_COMMIT(); }

        int chunk = s / KK, tap = s - chunk * KK;
        uint32_t aAh = smb + (chunk & 1) * (2 * A_CP * 2) + tap * (STR * 2);
        uint32_t aAm = aAh + A_CP * 2;
        uint32_t aBh = smb + (OFF_B + (s % 3) * (2 * B_CP)) * 2;
        uint32_t aBm = aBh + B_CP * 2;

#pragma unroll
        for (int kk = 0; kk < 2; kk++) {
            uint32_t ah[4][4], bh[4][2], bm[4][2];
#pragma unroll
            for (int mt = 0; mt < 4; mt++)
                LDM4(ah[mt][0], ah[mt][1], ah[mt][2], ah[mt][3], aAh + aoff[mt] + kk * 32);
#pragma unroll
            for (int np = 0; np < 2; np++)
                LDM4(bh[2 * np][0], bh[2 * np][1], bh[2 * np + 1][0], bh[2 * np + 1][1],
                     aBh + boff[np] + kk * 32);
#pragma unroll
            for (int mt = 0; mt < 4; mt++)
#pragma unroll
                for (int nt = 0; nt < 4; nt++) MMA_BF16(acc[mt][nt], ah[mt], bh[nt]);

#pragma unroll
            for (int np = 0; np < 2; np++)
                LDM4(bm[2 * np][0], bm[2 * np][1], bm[2 * np + 1][0], bm[2 * np + 1][1],
                     aBm + boff[np] + kk * 32);
#pragma unroll
            for (int mt = 0; mt < 4; mt++)
#pragma unroll
                for (int nt = 0; nt < 4; nt++) MMA_BF16(acc[mt][nt], ah[mt], bm[nt]);

#pragma unroll
            for (int mt = 0; mt < 4; mt++)
                LDM4(ah[mt][0], ah[mt][1], ah[mt][2], ah[mt][3], aAm + aoff[mt] + kk * 32);
#pragma unroll
            for (int mt = 0; mt < 4; mt++)
#pragma unroll
                for (int nt = 0; nt < 4; nt++) MMA_BF16(acc[mt][nt], ah[mt], bh[nt]);
        }
    }
    __syncthreads();

    // ---------------- epilogue: stage to smem, coalesced store ----------------------
    float* st = (float*)smbf;                 // 64 KB staging (fits)
    const int r = lane >> 2, cq = lane & 3;
#pragma unroll
    for (int mt = 0; mt < 4; mt++) {
        int R0 = wm * 64 + mt * 16 + r;
#pragma unroll
        for (int nt = 0; nt < 4; nt++) {
            int C = wn * 32 + nt * 8 + 2 * cq;
            st[R0 * 128 + C]           = acc[mt][nt][0];
            st[R0 * 128 + C + 1]       = acc[mt][nt][1];
            st[(R0 + 8) * 128 + C]     = acc[mt][nt][2];
            st[(R0 + 8) * 128 + C + 1] = acc[mt][nt][3];
        }
    }
    __syncthreads();
#pragma unroll
    for (int i = 0; i < 16; i++) {
        int f4 = tid + i * 256;               // 4096 float4 = 128x128
        int row = f4 >> 5, c4 = f4 & 31;
        *(float4*)(outc + (bT + t0 + row) * FILT + n0 + c4 * 4) = ((float4*)st)[f4];
    }
}

// ---------------- bias + relu + LN pass (warp per frame) ----------------------------
template <int MODE>    // 0: write bf16 hi/mid.  1: write fp32
__global__ void __launch_bounds__(256) ln_kernel(
    const float* __restrict__ gc,
    const float* __restrict__ bias, const float* __restrict__ gamma,
    const float* __restrict__ beta,
    float* __restrict__ outf,
    __nv_bfloat16* __restrict__ outh, __nv_bfloat16* __restrict__ outm)
{
    __shared__ float sB[FILT], sG[FILT], sE[FILT];
    int tid = threadIdx.x;
    if (tid < FILT) { sB[tid] = bias[tid]; sG[tid] = gamma[tid]; sE[tid] = beta[tid]; }
    __syncthreads();

    int wid = tid >> 5, lane = tid & 31;
    size_t frame = (size_t)blockIdx.x * 8 + wid;
    const float4* rp = (const float4*)(gc + frame * FILT);
    float4 v0 = rp[lane], v1 = rp[lane + 32];
    int ca = lane * 4, cb = 128 + lane * 4;

    float x[8];
    x[0] = fmaxf(v0.x + sB[ca], 0.f);     x[1] = fmaxf(v0.y + sB[ca + 1], 0.f);
    x[2] = fmaxf(v0.z + sB[ca + 2], 0.f); x[3] = fmaxf(v0.w + sB[ca + 3], 0.f);
    x[4] = fmaxf(v1.x + sB[cb], 0.f);     x[5] = fmaxf(v1.y + sB[cb + 1], 0.f);
    x[6] = fmaxf(v1.z + sB[cb + 2], 0.f); x[7] = fmaxf(v1.w + sB[cb + 3], 0.f);

    float s = 0.f, q = 0.f;
#pragma unroll
    for (int j = 0; j < 8; j++) { s += x[j]; q += x[j] * x[j]; }
#pragma unroll
    for (int off = 16; off > 0; off >>= 1) {
        s += __shfl_xor_sync(0xffffffffu, s, off);
        q += __shfl_xor_sync(0xffffffffu, q, off);
    }
    float m = s * (1.f / FILT);
    float rs = rsqrtf(q * (1.f / FILT) - m * m + 1e-5f);

    float y[8];
#pragma unroll
    for (int j = 0; j < 4; j++) y[j] = (x[j] - m) * rs * sG[ca + j] + sE[ca + j];
#pragma unroll
    for (int j = 0; j < 4; j++) y[4 + j] = (x[4 + j] - m) * rs * sG[cb + j] + sE[cb + j];

    if (MODE == 1) {
        float4* wp = (float4*)(outf + frame * FILT);
        wp[lane] = make_float4(y[0], y[1], y[2], y[3]);
        wp[lane + 32] = make_float4(y[4], y[5], y[6], y[7]);
    } else {
        uint2* hp = (uint2*)(outh + frame * FILT);
        uint2* mp = (uint2*)(outm + frame * FILT);
        hp[lane]      = make_uint2(pack_hi2(y[0], y[1]), pack_hi2(y[2], y[3]));
        hp[lane + 32] = make_uint2(pack_hi2(y[4], y[5]), pack_hi2(y[6], y[7]));
        mp[lane]      = make_uint2(pack_mid2(y[0], y[1]), pack_mid2(y[2], y[3]));
        mp[lane + 32] = make_uint2(pack_mid2(y[4], y[5]), pack_mid2(y[6], y[7]));
    }
}

// ---------------- pooling / mlp / expand --------------------------------------------
__global__ void phone_pool_kernel(const int* __restrict__ dur) {
    int b = blockIdx.y, p = blockIdx.x, c = threadIdx.x;
    int start = p ? g_pcum[b * PP + p - 1] : 0;
    int end = g_pcum[b * PP + p];
    if (start > TT) start = TT;
    if (end > TT) end = TT;
    float s = 0.f;
    for (int t = start; t < end; t++) s += g_x2[((size_t)(b * TT + t)) * FILT + c];
    int d = dur[b * PP + p]; if (d < 1) d = 1;
    g_ph[((size_t)(b * PP + p)) * FILT + c] = s / (float)d;
}
__global__ void word_pool_kernel(const int* __restrict__ wpl) {
    int b = blockIdx.y, w = blockIdx.x, c = threadIdx.x;
    int start = w ? g_wcum[b * WW + w - 1] : 0;
    int end = g_wcum[b * WW + w];
    if (start > PP) start = PP;
    if (end > PP) end = PP;
    float s = 0.f;
    for (int p = start; p < end; p++) s += g_ph[((size_t)(b * PP + p)) * FILT + c];
    int d = wpl[b * WW + w]; if (d < 1) d = 1;
    g_wd[((size_t)(b * WW + w)) * FILT + c] = s / (float)d;
}
__global__ void __launch_bounds__(256) mlp_kernel(
    const float* __restrict__ w1, const float* __restrict__ b1,
    const float* __restrict__ w2, const float* __restrict__ b2)
{
    __shared__ float sh[32 * FILT];
    int b = blockIdx.y, w0 = blockIdx.x * 32, o = threadIdx.x;
    for (int idx = o; idx < 32 * FILT; idx += 256)
        sh[idx] = g_wd[((size_t)(b * WW + w0)) * FILT + idx];
    __syncthreads();
    float acc[32];
    float bv = b1[o];
#pragma unroll
    for (int m = 0; m < 32; m++) acc[m] = bv;
    for (int i = 0; i < FILT; i++) {
        float wv = w1[i * FILT + o];
#pragma unroll
        for (int m = 0; m < 32; m++) acc[m] += sh[m * FILT + i] * wv;
    }
    __syncthreads();
#pragma unroll
    for (int m = 0; m < 32; m++) sh[m * FILT + o] = fmaxf(acc[m], 0.f);
    __syncthreads();
    int oo = o & (PDIM - 1);
    int mg = o >> 6;
    for (int m = mg * 8; m < mg * 8 + 8; m++) {
        float a = b2[oo];
        for (int i = 0; i < FILT; i++) a += sh[m * FILT + i] * w2[i * PDIM + oo];
        g_z[((size_t)(b * WW + w0 + m)) * PDIM + oo] = fmaxf(a, 0.f);
    }
}
__global__ void expand_kernel(const unsigned char* __restrict__ mask, float* __restrict__ out) {
    int b = blockIdx.y, p = blockIdx.x, o = threadIdx.x;
    const int* wc = g_wcum + b * WW;
    int lo = 0, hi = WW;
    while (lo < hi) { int mid = (lo + hi) >> 1; if (wc[mid] <= p) lo = mid + 1; else hi = mid; }
    int wid = lo; if (wid > WW - 1) wid = WW - 1;
    float v = g_z[((size_t)(b * WW + wid)) * PDIM + o];
    if (mask[b * PP + p]) v = 0.f;
    out[((size_t)(b * PP + p)) * PDIM + o] = v;
}

// ---------------- host launch -------------------------------------------------------
extern "C" void kernel_launch(void* const* d_in, const int* in_sizes, int n_in,
                              void* d_out, int out_size)
{
    const unsigned char* mask = (const unsigned char*)d_in[0];
    const float* mels = (const float*)d_in[1];
    const int* durations = (const int*)d_in[3];
    const int* wpl = (const int*)d_in[4];
    const float* c1w = (const float*)d_in[5];
    const float* c1b = (const float*)d_in[6];
    const float* l1g = (const float*)d_in[7];
    const float* l1b = (const float*)d_in[8];
    const float* c2w = (const float*)d_in[9];
    const float* c2b = (const float*)d_in[10];
    const float* l2g = (const float*)d_in[11];
    const float* l2b = (const float*)d_in[12];
    const float* w1 = (const float*)d_in[13];
    const float* b1 = (const float*)d_in[14];
    const float* w2 = (const float*)d_in[15];
    const float* b2 = (const float*)d_in[16];
    float* out = (float*)d_out;

    void *p_melhi, *p_melmid, *p_x1hi, *p_x1mid, *p_craw, *p_x2;
    void *p_w1h, *p_w1m, *p_w2h, *p_w2m;
    cudaGetSymbolAddress(&p_melhi, g_melhi);
    cudaGetSymbolAddress(&p_melmid, g_melmid);
    cudaGetSymbolAddress(&p_x1hi, g_x1hi);
    cudaGetSymbolAddress(&p_x1mid, g_x1mid);
    cudaGetSymbolAddress(&p_craw, g_craw);
    cudaGetSymbolAddress(&p_x2, g_x2);
    cudaGetSymbolAddress(&p_w1h, g_w1h);
    cudaGetSymbolAddress(&p_w1m, g_w1m);
    cudaGetSymbolAddress(&p_w2h, g_w2h);
    cudaGetSymbolAddress(&p_w2m, g_w2m);

    cudaFuncSetAttribute(conv_mma<3>, cudaFuncAttributeMaxDynamicSharedMemorySize, CONV_SMEM);
    cudaFuncSetAttribute(conv_mma<8>, cudaFuncAttributeMaxDynamicSharedMemorySize, CONV_SMEM);

    mel_split_kernel<<<(int)(((size_t)BB * TT * 96 + 255) / 256), 256>>>(mels);
    wsplit_kernel<NMEL, 96><<<(KK * FILT * 96 + 255) / 256, 256>>>(
        c1w, (__nv_bfloat16*)p_w1h, (__nv_bfloat16*)p_w1m);
    wsplit_kernel<FILT, FILT><<<(KK * FILT * FILT + 255) / 256, 256>>>(
        c2w, (__nv_bfloat16*)p_w2h, (__nv_bfloat16*)p_w2m);
    scan_kernel<<<BB, 32>>>(durations, wpl);

    dim3 cgrid(TT / 128, 2, BB);
    conv_mma<3><<<cgrid, 256, CONV_SMEM>>>(
        (const __nv_bfloat16*)p_melhi, (const __nv_bfloat16*)p_melmid,
        (const __nv_bfloat16*)p_w1h, (const __nv_bfloat16*)p_w1m, (float*)p_craw);
    ln_kernel<0><<<BB * TT / 8, 256>>>((const float*)p_craw, c1b, l1g, l1b,
        nullptr, (__nv_bfloat16*)p_x1hi, (__nv_bfloat16*)p_x1mid);
    conv_mma<8><<<cgrid, 256, CONV_SMEM>>>(
        (const __nv_bfloat16*)p_x1hi, (const __nv_bfloat16*)p_x1mid,
        (const __nv_bfloat16*)p_w2h, (const __nv_bfloat16*)p_w2m, (float*)p_craw);
    ln_kernel<1><<<BB * TT / 8, 256>>>((const float*)p_craw, c2b, l2g, l2b,
        (float*)p_x2, nullptr, nullptr);

    phone_pool_kernel<<<dim3(PP, BB), FILT>>>(durations);
    word_pool_kernel<<<dim3(WW, BB), FILT>>>(wpl);
    mlp_kernel<<<dim3(WW / 32, BB), 256>>>(w1, b1, w2, b2);
    expand_kernel<<<dim3(PP, BB), PDIM>>>(mask, out);
}

// round 7
// speedup vs baseline: 1.3982x; 1.3982x over previous
#include <cuda_runtime.h>
#include <cuda_fp16.h>
#include <cstdint>

#define BB 32
#define TT 4096
#define PP 512
#define WW 128
#define NMEL 80
#define FILT 256
#define PDIM 64
#define KK 9
#define PAD 4

#define STR 40                        // smem row stride (fp16), conflict-free
#define A_ROWS 136                    // 128 + 2*PAD halo
#define A_CP 5440                     // A_ROWS*STR elems per copy
#define B_CP 5120                     // 128*STR elems
// A chunkbuf k at k*(2*A_CP) (hi, mid); B ring r at OFF_B + r*B_CP
#define OFF_B 21760
#define CONV_SMEM ((OFF_B + 3 * B_CP) * 2)    // 74240 bytes -> 2 CTAs/SM

// ---------------- device scratch ----------------------------------------------------
__device__ __half g_melhi[(size_t)BB * TT * 96];
__device__ __half g_melmid[(size_t)BB * TT * 96];
__device__ __half g_x1hi[(size_t)BB * TT * FILT];
__device__ __half g_x1mid[(size_t)BB * TT * FILT];
__device__ float g_craw[(size_t)BB * TT * FILT];
__device__ float g_x2[(size_t)BB * TT * FILT];
__device__ __half g_w1h[KK * FILT * 96];
__device__ __half g_w2h[KK * FILT * FILT];
__device__ float g_ph[(size_t)BB * PP * FILT];
__device__ float g_wd[(size_t)BB * WW * FILT];
__device__ float g_z [(size_t)BB * WW * PDIM];
__device__ int   g_pcum[BB * PP];
__device__ int   g_wcum[BB * WW];

// ---------------- helpers ------------------------------------------------------------
__device__ __forceinline__ uint32_t smem_u32(const void* p) {
    return (uint32_t)__cvta_generic_to_shared(p);
}
#define CP16(dst_u32, src_ptr) \
    asm volatile("cp.async.cg.shared.global [%0], [%1], 16;" :: "r"(dst_u32), "l"(src_ptr) : "memory")
#define CP_COMMIT() asm volatile("cp.async.commit_group;" ::: "memory")
#define CP_WAIT0()  asm volatile("cp.async.wait_group 0;" ::: "memory")
#define CP_WAIT1()  asm volatile("cp.async.wait_group 1;" ::: "memory")

#define MMA_F16(d, a, b) \
    asm volatile("mma.sync.aligned.m16n8k16.row.col.f32.f16.f16.f32 " \
        "{%0,%1,%2,%3},{%4,%5,%6,%7},{%8,%9},{%0,%1,%2,%3};" \
        : "+f"((d)[0]), "+f"((d)[1]), "+f"((d)[2]), "+f"((d)[3]) \
        : "r"((a)[0]), "r"((a)[1]), "r"((a)[2]), "r"((a)[3]), "r"((b)[0]), "r"((b)[1]))

#define LDM4(r0, r1, r2, r3, addr) \
    asm volatile("ldmatrix.sync.aligned.m8n8.x4.shared.b16 {%0,%1,%2,%3}, [%4];" \
        : "=r"(r0), "=r"(r1), "=r"(r2), "=r"(r3) : "r"(addr))

__device__ __forceinline__ uint32_t pack_hi2(float x0, float x1) {
    __half2 t(__float2half_rn(x0), __float2half_rn(x1));
    return *reinterpret_cast<uint32_t*>(&t);
}
__device__ __forceinline__ uint32_t pack_mid2(float x0, float x1) {
    float h0 = __half2float(__float2half_rn(x0));
    float h1 = __half2float(__float2half_rn(x1));
    __half2 t(__float2half_rn(x0 - h0), __float2half_rn(x1 - h1));
    return *reinterpret_cast<uint32_t*>(&t);
}

// ---------------- prep kernels -------------------------------------------------------
__global__ void mel_split_kernel(const float* __restrict__ mels) {
    size_t i = (size_t)blockIdx.x * blockDim.x + threadIdx.x;
    if (i < (size_t)BB * TT * 96) {
        size_t t = i / 96;
        int ci = (int)(i % 96);
        float x = (ci < NMEL) ? mels[t * NMEL + ci] : 0.f;
        __half h = __float2half_rn(x);
        g_melhi[i] = h;
        g_melmid[i] = __float2half_rn(x - __half2float(h));
    }
}
template <int CIN, int CINP>
__global__ void wsplit_kernel(const float* __restrict__ w, __half* __restrict__ wh) {
    int i = blockIdx.x * blockDim.x + threadIdx.x;      // [tap][co][ci-padded]
    if (i < KK * FILT * CINP) {
        int ci = i % CINP;
        int co = (i / CINP) % FILT;
        int tap = i / (CINP * FILT);
        float x = (ci < CIN) ? w[(co * CIN + ci) * KK + tap] : 0.f;
        wh[i] = __float2half_rn(x);
    }
}
__global__ void scan_kernel(const int* __restrict__ dur, const int* __restrict__ wpl) {
    int b = blockIdx.x, lane = threadIdx.x;             // 32 threads/block
    int v[16], s = 0;
#pragma unroll
    for (int i = 0; i < 16; i++) { v[i] = dur[b * PP + lane * 16 + i]; s += v[i]; }
    int inc = s;
#pragma unroll
    for (int off = 1; off < 32; off <<= 1) {
        int t = __shfl_up_sync(0xffffffffu, inc, off);
        if (lane >= off) inc += t;
    }
    int base = inc - s, run = 0;
#pragma unroll
    for (int i = 0; i < 16; i++) { run += v[i]; g_pcum[b * PP + lane * 16 + i] = base + run; }
    int w[4]; s = 0;
#pragma unroll
    for (int i = 0; i < 4; i++) { w[i] = wpl[b * WW + lane * 4 + i]; s += w[i]; }
    inc = s;
#pragma unroll
    for (int off = 1; off < 32; off <<= 1) {
        int t = __shfl_up_sync(0xffffffffu, inc, off);
        if (lane >= off) inc += t;
    }
    base = inc - s; run = 0;
#pragma unroll
    for (int i = 0; i < 4; i++) { run += w[i]; g_wcum[b * WW + lane * 4 + i] = base + run; }
}

// ---------------- conv via fp16x2 mma.sync, halo-resident A, 2 CTAs/SM ---------------
template <int NCH>     // cin chunks of 32: conv1=3 (padded 96), conv2=8
__global__ void __launch_bounds__(256, 2) conv_mma(
    const __half* __restrict__ Ahi, const __half* __restrict__ Amid,
    const __half* __restrict__ Bh16,
    float* __restrict__ outc)
{
    constexpr int CINP = NCH * 32;
    constexpr int NST = NCH * KK;
    extern __shared__ __half smhf[];

    const int tid = threadIdx.x;
    const int wid = tid >> 5, lane = tid & 31;
    const int wm = wid & 1, wn = wid >> 1;              // 2m x 4n warps
    const int t0 = blockIdx.x * 128;
    const int n0 = blockIdx.y * 128;
    const size_t bT = (size_t)blockIdx.z * TT;
    const uint32_t smb = smem_u32(smhf);

    float acc[4][4][4];
#pragma unroll
    for (int mt = 0; mt < 4; mt++)
#pragma unroll
        for (int nt = 0; nt < 4; nt++)
#pragma unroll
            for (int q = 0; q < 4; q++) acc[mt][nt][q] = 0.f;

    // ldmatrix lane offsets
    const int a_l = ((lane >> 3) & 1) * 8 + (lane & 7);
    const int a_k = (lane >> 4) * 8;
    const int b_l = (lane >> 4) * 8 + (lane & 7);
    const int b_k = ((lane >> 3) & 1) * 8;
    uint32_t aoff[4], boff[2];
#pragma unroll
    for (int mt = 0; mt < 4; mt++)
        aoff[mt] = ((wm * 64 + mt * 16 + a_l) * STR + a_k) * 2;
#pragma unroll
    for (int np = 0; np < 2; np++)
        boff[np] = ((wn * 32 + np * 16 + b_l) * STR + b_k) * 2;

    auto issue_loads = [&](int s) {
        int chunk = s / KK, tap = s - chunk * KK;
        __half* sB = smhf + OFF_B + (s % 3) * B_CP;
#pragma unroll
        for (int j = 0; j < 2; j++) {
            int q = tid + j * 256;                      // 0..511
            int row = q >> 2, c16 = q & 3;
            const __half* src = Bh16
                + ((size_t)tap * FILT + n0 + row) * CINP + chunk * 32 + c16 * 8;
            CP16(smem_u32(sB + row * STR + c16 * 8), src);
        }
        if (tap == 0) {
            __half* sA = smhf + (chunk & 1) * (2 * A_CP);
#pragma unroll
            for (int j = 0; j < 5; j++) {
                int q = tid + j * 256;
                if (q < 1088) {
                    int copy = (q >= 544) ? 1 : 0;
                    int rem = q - copy * 544;
                    int row = rem >> 2, c16 = rem & 3;
                    int trow = t0 + row - PAD;
                    __half* dst = sA + copy * A_CP + row * STR + c16 * 8;
                    if (trow >= 0 && trow < TT) {
                        const __half* src = (copy ? Amid : Ahi)
                            + (bT + trow) * CINP + chunk * 32 + c16 * 8;
                        CP16(smem_u32(dst), src);
                    } else {
                        *(uint4*)dst = make_uint4(0, 0, 0, 0);
                    }
                }
            }
        }
    };

    issue_loads(0); CP_COMMIT();
    issue_loads(1); CP_COMMIT();

    for (int s = 0; s < NST; s++) {
        if (s + 1 < NST) CP_WAIT1(); else CP_WAIT0();
        __syncthreads();
        if (s + 2 < NST) { issue_loads(s + 2); CP_COMMIT(); }

        int chunk = s / KK, tap = s - chunk * KK;
        uint32_t aAh = smb + (chunk & 1) * (2 * A_CP * 2) + tap * (STR * 2);
        uint32_t aAm = aAh + A_CP * 2;
        uint32_t aBh = smb + (OFF_B + (s % 3) * B_CP) * 2;

#pragma unroll
        for (int kk = 0; kk < 2; kk++) {
            uint32_t ah[4][4], bh[4][2];
#pragma unroll
            for (int mt = 0; mt < 4; mt++)
                LDM4(ah[mt][0], ah[mt][1], ah[mt][2], ah[mt][3], aAh + aoff[mt] + kk * 32);
#pragma unroll
            for (int np = 0; np < 2; np++)
                LDM4(bh[2 * np][0], bh[2 * np][1], bh[2 * np + 1][0], bh[2 * np + 1][1],
                     aBh + boff[np] + kk * 32);
#pragma unroll
            for (int mt = 0; mt < 4; mt++)
#pragma unroll
                for (int nt = 0; nt < 4; nt++) MMA_F16(acc[mt][nt], ah[mt], bh[nt]);

#pragma unroll
            for (int mt = 0; mt < 4; mt++)
                LDM4(ah[mt][0], ah[mt][1], ah[mt][2], ah[mt][3], aAm + aoff[mt] + kk * 32);
#pragma unroll
            for (int mt = 0; mt < 4; mt++)
#pragma unroll
                for (int nt = 0; nt < 4; nt++) MMA_F16(acc[mt][nt], ah[mt], bh[nt]);
        }
    }
    __syncthreads();

    // ---------------- epilogue: stage to smem, coalesced store ----------------------
    float* st = (float*)smhf;                 // 64 KB staging (fits in 74240)
    const int r = lane >> 2, cq = lane & 3;
#pragma unroll
    for (int mt = 0; mt < 4; mt++) {
        int R0 = wm * 64 + mt * 16 + r;
#pragma unroll
        for (int nt = 0; nt < 4; nt++) {
            int C = wn * 32 + nt * 8 + 2 * cq;
            st[R0 * 128 + C]           = acc[mt][nt][0];
            st[R0 * 128 + C + 1]       = acc[mt][nt][1];
            st[(R0 + 8) * 128 + C]     = acc[mt][nt][2];
            st[(R0 + 8) * 128 + C + 1] = acc[mt][nt][3];
        }
    }
    __syncthreads();
#pragma unroll
    for (int i = 0; i < 16; i++) {
        int f4 = tid + i * 256;               // 4096 float4 = 128x128
        int row = f4 >> 5, c4 = f4 & 31;
        *(float4*)(outc + (bT + t0 + row) * FILT + n0 + c4 * 4) = ((float4*)st)[f4];
    }
}

// ---------------- bias + relu + LN pass (warp per frame) ----------------------------
template <int MODE>    // 0: write fp16 hi/mid.  1: write fp32
__global__ void __launch_bounds__(256) ln_kernel(
    const float* __restrict__ gc,
    const float* __restrict__ bias, const float* __restrict__ gamma,
    const float* __restrict__ beta,
    float* __restrict__ outf,
    __half* __restrict__ outh, __half* __restrict__ outm)
{
    __shared__ float sB[FILT], sG[FILT], sE[FILT];
    int tid = threadIdx.x;
    if (tid < FILT) { sB[tid] = bias[tid]; sG[tid] = gamma[tid]; sE[tid] = beta[tid]; }
    __syncthreads();

    int wid = tid >> 5, lane = tid & 31;
    size_t frame = (size_t)blockIdx.x * 8 + wid;
    const float4* rp = (const float4*)(gc + frame * FILT);
    float4 v0 = rp[lane], v1 = rp[lane + 32];
    int ca = lane * 4, cb = 128 + lane * 4;

    float x[8];
    x[0] = fmaxf(v0.x + sB[ca], 0.f);     x[1] = fmaxf(v0.y + sB[ca + 1], 0.f);
    x[2] = fmaxf(v0.z + sB[ca + 2], 0.f); x[3] = fmaxf(v0.w + sB[ca + 3], 0.f);
    x[4] = fmaxf(v1.x + sB[cb], 0.f);     x[5] = fmaxf(v1.y + sB[cb + 1], 0.f);
    x[6] = fmaxf(v1.z + sB[cb + 2], 0.f); x[7] = fmaxf(v1.w + sB[cb + 3], 0.f);

    float s = 0.f, q = 0.f;
#pragma unroll
    for (int j = 0; j < 8; j++) { s += x[j]; q += x[j] * x[j]; }
#pragma unroll
    for (int off = 16; off > 0; off >>= 1) {
        s += __shfl_xor_sync(0xffffffffu, s, off);
        q += __shfl_xor_sync(0xffffffffu, q, off);
    }
    float m = s * (1.f / FILT);
    float rs = rsqrtf(q * (1.f / FILT) - m * m + 1e-5f);

    float y[8];
#pragma unroll
    for (int j = 0; j < 4; j++) y[j] = (x[j] - m) * rs * sG[ca + j] + sE[ca + j];
#pragma unroll
    for (int j = 0; j < 4; j++) y[4 + j] = (x[4 + j] - m) * rs * sG[cb + j] + sE[cb + j];

    if (MODE == 1) {
        float4* wp = (float4*)(outf + frame * FILT);
        wp[lane] = make_float4(y[0], y[1], y[2], y[3]);
        wp[lane + 32] = make_float4(y[4], y[5], y[6], y[7]);
    } else {
        uint2* hp = (uint2*)(outh + frame * FILT);
        uint2* mp = (uint2*)(outm + frame * FILT);
        hp[lane]      = make_uint2(pack_hi2(y[0], y[1]), pack_hi2(y[2], y[3]));
        hp[lane + 32] = make_uint2(pack_hi2(y[4], y[5]), pack_hi2(y[6], y[7]));
        mp[lane]      = make_uint2(pack_mid2(y[0], y[1]), pack_mid2(y[2], y[3]));
        mp[lane + 32] = make_uint2(pack_mid2(y[4], y[5]), pack_mid2(y[6], y[7]));
    }
}

// ---------------- pooling / mlp / expand --------------------------------------------
__global__ void phone_pool_kernel(const int* __restrict__ dur) {
    int b = blockIdx.y, p = blockIdx.x, c = threadIdx.x;
    int start = p ? g_pcum[b * PP + p - 1] : 0;
    int end = g_pcum[b * PP + p];
    if (start > TT) start = TT;
    if (end > TT) end = TT;
    float s = 0.f;
    for (int t = start; t < end; t++) s += g_x2[((size_t)(b * TT + t)) * FILT + c];
    int d = dur[b * PP + p]; if (d < 1) d = 1;
    g_ph[((size_t)(b * PP + p)) * FILT + c] = s / (float)d;
}
__global__ void word_pool_kernel(const int* __restrict__ wpl) {
    int b = blockIdx.y, w = blockIdx.x, c = threadIdx.x;
    int start = w ? g_wcum[b * WW + w - 1] : 0;
    int end = g_wcum[b * WW + w];
    if (start > PP) start = PP;
    if (end > PP) end = PP;
    float s = 0.f;
    for (int p = start; p < end; p++) s += g_ph[((size_t)(b * PP + p)) * FILT + c];
    int d = wpl[b * WW + w]; if (d < 1) d = 1;
    g_wd[((size_t)(b * WW + w)) * FILT + c] = s / (float)d;
}
__global__ void __launch_bounds__(256) mlp_kernel(
    const float* __restrict__ w1, const float* __restrict__ b1,
    const float* __restrict__ w2, const float* __restrict__ b2)
{
    __shared__ float sh[32 * FILT];
    int b = blockIdx.y, w0 = blockIdx.x * 32, o = threadIdx.x;
    for (int idx = o; idx < 32 * FILT; idx += 256)
        sh[idx] = g_wd[((size_t)(b * WW + w0)) * FILT + idx];
    __syncthreads();
    float acc[32];
    float bv = b1[o];
#pragma unroll
    for (int m = 0; m < 32; m++) acc[m] = bv;
    for (int i = 0; i < FILT; i++) {
        float wv = w1[i * FILT + o];
#pragma unroll
        for (int m = 0; m < 32; m++) acc[m] += sh[m * FILT + i] * wv;
    }
    __syncthreads();
#pragma unroll
    for (int m = 0; m < 32; m++) sh[m * FILT + o] = fmaxf(acc[m], 0.f);
    __syncthreads();
    int oo = o & (PDIM - 1);
    int mg = o >> 6;
    for (int m = mg * 8; m < mg * 8 + 8; m++) {
        float a = b2[oo];
        for (int i = 0; i < FILT; i++) a += sh[m * FILT + i] * w2[i * PDIM + oo];
        g_z[((size_t)(b * WW + w0 + m)) * PDIM + oo] = fmaxf(a, 0.f);
    }
}
__global__ void expand_kernel(const unsigned char* __restrict__ mask, float* __restrict__ out) {
    int b = blockIdx.y, p = blockIdx.x, o = threadIdx.x;
    const int* wc = g_wcum + b * WW;
    int lo = 0, hi = WW;
    while (lo < hi) { int mid = (lo + hi) >> 1; if (wc[mid] <= p) lo = mid + 1; else hi = mid; }
    int wid = lo; if (wid > WW - 1) wid = WW - 1;
    float v = g_z[((size_t)(b * WW + wid)) * PDIM + o];
    if (mask[b * PP + p]) v = 0.f;
    out[((size_t)(b * PP + p)) * PDIM + o] = v;
}

// ---------------- host launch -------------------------------------------------------
extern "C" void kernel_launch(void* const* d_in, const int* in_sizes, int n_in,
                              void* d_out, int out_size)
{
    const unsigned char* mask = (const unsigned char*)d_in[0];
    const float* mels = (const float*)d_in[1];
    const int* durations = (const int*)d_in[3];
    const int* wpl = (const int*)d_in[4];
    const float* c1w = (const float*)d_in[5];
    const float* c1b = (const float*)d_in[6];
    const float* l1g = (const float*)d_in[7];
    const float* l1b = (const float*)d_in[8];
    const float* c2w = (const float*)d_in[9];
    const float* c2b = (const float*)d_in[10];
    const float* l2g = (const float*)d_in[11];
    const float* l2b = (const float*)d_in[12];
    const float* w1 = (const float*)d_in[13];
    const float* b1 = (const float*)d_in[14];
    const float* w2 = (const float*)d_in[15];
    const float* b2 = (const float*)d_in[16];
    float* out = (float*)d_out;

    void *p_melhi, *p_melmid, *p_x1hi, *p_x1mid, *p_craw, *p_x2, *p_w1h, *p_w2h;
    cudaGetSymbolAddress(&p_melhi, g_melhi);
    cudaGetSymbolAddress(&p_melmid, g_melmid);
    cudaGetSymbolAddress(&p_x1hi, g_x1hi);
    cudaGetSymbolAddress(&p_x1mid, g_x1mid);
    cudaGetSymbolAddress(&p_craw, g_craw);
    cudaGetSymbolAddress(&p_x2, g_x2);
    cudaGetSymbolAddress(&p_w1h, g_w1h);
    cudaGetSymbolAddress(&p_w2h, g_w2h);

    cudaFuncSetAttribute(conv_mma<3>, cudaFuncAttributeMaxDynamicSharedMemorySize, CONV_SMEM);
    cudaFuncSetAttribute(conv_mma<8>, cudaFuncAttributeMaxDynamicSharedMemorySize, CONV_SMEM);

    mel_split_kernel<<<(int)(((size_t)BB * TT * 96 + 255) / 256), 256>>>(mels);
    wsplit_kernel<NMEL, 96><<<(KK * FILT * 96 + 255) / 256, 256>>>(c1w, (__half*)p_w1h);
    wsplit_kernel<FILT, FILT><<<(KK * FILT * FILT + 255) / 256, 256>>>(c2w, (__half*)p_w2h);
    scan_kernel<<<BB, 32>>>(durations, wpl);

    dim3 cgrid(TT / 128, 2, BB);
    conv_mma<3><<<cgrid, 256, CONV_SMEM>>>(
        (const __half*)p_melhi, (const __half*)p_melmid,
        (const __half*)p_w1h, (float*)p_craw);
    ln_kernel<0><<<BB * TT / 8, 256>>>((const float*)p_craw, c1b, l1g, l1b,
        nullptr, (__half*)p_x1hi, (__half*)p_x1mid);
    conv_mma<8><<<cgrid, 256, CONV_SMEM>>>(
        (const __half*)p_x1hi, (const __half*)p_x1mid,
        (const __half*)p_w2h, (float*)p_craw);
    ln_kernel<1><<<BB * TT / 8, 256>>>((const float*)p_craw, c2b, l2g, l2b,
        (float*)p_x2, nullptr, nullptr);

    phone_pool_kernel<<<dim3(PP, BB), FILT>>>(durations);
    word_pool_kernel<<<dim3(WW, BB), FILT>>>(wpl);
    mlp_kernel<<<dim3(WW / 32, BB), 256>>>(w1, b1, w2, b2);
    expand_kernel<<<dim3(PP, BB), PDIM>>>(mask, out);
}